// round 1
// baseline (speedup 1.0000x reference)
#include <cuda_runtime.h>
#include <math.h>

#define B 16
#define LQ 2048
#define EMB1 1024
#define EMB2 768
#define HDIM 1024
#define NHEAD 16
#define DH 64

// Scratch (static device globals; no allocation in kernel_launch).
__device__ float g_K[B * HDIM];
__device__ float g_V[B * HDIM];
__device__ float g_Weff[B * NHEAD * EMB1];
__device__ float g_c[B * NHEAD];

// ---------------------------------------------------------------------------
// Kernel 1: K[b,j] = emb2[b]·Wk[j] + bk[j], V likewise. One warp per j,
// looping over batches so each Wk/Wv row is loaded once into registers.
// ---------------------------------------------------------------------------
__global__ void kv_kernel(const float* __restrict__ emb2,
                          const float* __restrict__ Wk, const float* __restrict__ bk,
                          const float* __restrict__ Wv, const float* __restrict__ bv) {
    int gwarp = (blockIdx.x * blockDim.x + threadIdx.x) >> 5;
    int lane = threadIdx.x & 31;
    if (gwarp >= HDIM) return;
    int j = gwarp;

    float wk[24], wv[24];
#pragma unroll
    for (int i = 0; i < 24; i++) {
        wk[i] = Wk[j * EMB2 + i * 32 + lane];
        wv[i] = Wv[j * EMB2 + i * 32 + lane];
    }
    float bkj = (lane == 0) ? bk[j] : 0.f;
    float bvj = (lane == 0) ? bv[j] : 0.f;

    for (int b = 0; b < B; b++) {
        float ak = 0.f, av = 0.f;
#pragma unroll
        for (int i = 0; i < 24; i++) {
            float e = emb2[b * EMB2 + i * 32 + lane];
            ak = fmaf(e, wk[i], ak);
            av = fmaf(e, wv[i], av);
        }
#pragma unroll
        for (int off = 16; off; off >>= 1) {
            ak += __shfl_xor_sync(0xffffffffu, ak, off);
            av += __shfl_xor_sync(0xffffffffu, av, off);
        }
        if (lane == 0) {
            g_K[b * HDIM + j] = ak + bkj;
            g_V[b * HDIM + j] = av + bvj;
        }
    }
}

// ---------------------------------------------------------------------------
// Kernel 2: Weff[b,h,e] = sum_d Wq[h*64+d, e] * K[b, h*64+d].
// Block = (e-chunk of 128, head h). Wq chunk staged in smem, reused for all b.
// ---------------------------------------------------------------------------
__global__ void weff_kernel(const float* __restrict__ Wq) {
    __shared__ float Wq_s[DH * 128];
    __shared__ float Ks[DH];
    int h = blockIdx.y;
    int e0 = blockIdx.x * 128;
    int tid = threadIdx.x;

#pragma unroll 8
    for (int d = 0; d < DH; d++)
        Wq_s[d * 128 + tid] = Wq[(h * DH + d) * EMB1 + e0 + tid];

    for (int b = 0; b < B; b++) {
        __syncthreads();
        if (tid < DH) Ks[tid] = g_K[b * HDIM + h * DH + tid];
        __syncthreads();
        float a = 0.f;
#pragma unroll 16
        for (int d = 0; d < DH; d++)
            a = fmaf(Wq_s[d * 128 + tid], Ks[d], a);
        g_Weff[(b * NHEAD + h) * EMB1 + e0 + tid] = a;
    }
}

// ---------------------------------------------------------------------------
// Kernel 3: c[b,h] = sum_d bq[h*64+d] * K[b, h*64+d]. One thread per (b,h).
// ---------------------------------------------------------------------------
__global__ void c_kernel(const float* __restrict__ bq) {
    int p = threadIdx.x;         // p = b*16 + h, 256 threads
    int b = p >> 4, h = p & 15;
    float a = 0.f;
#pragma unroll 16
    for (int d = 0; d < DH; d++)
        a = fmaf(bq[h * DH + d], g_K[b * HDIM + h * DH + d], a);
    g_c[p] = a;
}

// ---------------------------------------------------------------------------
// Kernel 4 (main): one warp per query row.
//   att[h] = emb1_row · Weff[b,h] + c[b,h]
//   out_row[h*64+d] = sigmoid(att[h]) * V[b, h*64+d]
// Weff[b] (64KB) + V[b] (4KB) + c[b] staged in dynamic smem per block.
// ---------------------------------------------------------------------------
__global__ __launch_bounds__(256) void main_kernel(const float* __restrict__ emb1,
                                                   float* __restrict__ out) {
    extern __shared__ float sm[];
    float* Weff_s = sm;                    // NHEAD*EMB1 = 16384 floats
    float* V_s = sm + NHEAD * EMB1;        // 1024 floats
    float* c_s = V_s + HDIM;               // 16 floats

    int b = blockIdx.y;
    int tid = threadIdx.x;

    // Cooperative staging
    {
        const float4* Wg = (const float4*)(g_Weff + (size_t)b * NHEAD * EMB1);
        float4* Ws4 = (float4*)Weff_s;
#pragma unroll
        for (int i = 0; i < NHEAD * EMB1 / 4 / 256; i++)
            Ws4[i * 256 + tid] = Wg[i * 256 + tid];
        const float4* Vg = (const float4*)(g_V + (size_t)b * HDIM);
        if (tid < HDIM / 4) ((float4*)V_s)[tid] = Vg[tid];
        if (tid < NHEAD) c_s[tid] = g_c[b * NHEAD + tid];
    }
    __syncthreads();

    int warp = tid >> 5, lane = tid & 31;
    const float4* Ws4 = (const float4*)Weff_s;
    const float4* Vs4 = (const float4*)V_s;
    int hi = (lane >> 4) & 1;

    for (int r = warp; r < 64; r += 8) {
        int q = blockIdx.x * 64 + r;
        const float4* xr = (const float4*)(emb1 + ((size_t)b * LQ + q) * EMB1);

        float4 x[8];
#pragma unroll
        for (int i = 0; i < 8; i++) x[i] = xr[i * 32 + lane];

        float acc[NHEAD];
#pragma unroll
        for (int h = 0; h < NHEAD; h++) acc[h] = 0.f;

#pragma unroll
        for (int i = 0; i < 8; i++) {
#pragma unroll
            for (int h = 0; h < NHEAD; h++) {
                float4 w = Ws4[h * 256 + i * 32 + lane];
                acc[h] = fmaf(x[i].x, w.x, acc[h]);
                acc[h] = fmaf(x[i].y, w.y, acc[h]);
                acc[h] = fmaf(x[i].z, w.z, acc[h]);
                acc[h] = fmaf(x[i].w, w.w, acc[h]);
            }
        }

        // Butterfly reduce all 16 head accumulators across the warp.
#pragma unroll
        for (int off = 16; off; off >>= 1) {
#pragma unroll
            for (int h = 0; h < NHEAD; h++)
                acc[h] += __shfl_xor_sync(0xffffffffu, acc[h], off);
        }

        float sig[NHEAD];
#pragma unroll
        for (int h = 0; h < NHEAD; h++)
            sig[h] = 1.f / (1.f + __expf(-(acc[h] + c_s[h])));

        float4* orow = (float4*)(out + ((size_t)b * LQ + q) * EMB1);
#pragma unroll
        for (int i = 0; i < 8; i++) {
            // float4 index i*32+lane covers hdim element 4*(i*32+lane);
            // head = (i*32+lane)>>4 = 2*i + (lane>=16)
            float s = sig[2 * i + hi];
            float4 v = Vs4[i * 32 + lane];
            float4 o;
            o.x = s * v.x; o.y = s * v.y; o.z = s * v.z; o.w = s * v.w;
            orow[i * 32 + lane] = o;
        }
    }
}

// ---------------------------------------------------------------------------
extern "C" void kernel_launch(void* const* d_in, const int* in_sizes, int n_in,
                              void* d_out, int out_size) {
    const float* emb1 = (const float*)d_in[0];
    const float* emb2 = (const float*)d_in[1];
    const float* Wq   = (const float*)d_in[2];
    const float* bq   = (const float*)d_in[3];
    const float* Wk   = (const float*)d_in[4];
    const float* bk   = (const float*)d_in[5];
    const float* Wv   = (const float*)d_in[6];
    const float* bv   = (const float*)d_in[7];
    float* out = (float*)d_out;

    // K/V projection: 1024 warps, 8 warps per block.
    kv_kernel<<<HDIM / 8, 256>>>(emb2, Wk, bk, Wv, bv);

    // Weff fold: (8 e-chunks, 16 heads), 128 threads.
    weff_kernel<<<dim3(EMB1 / 128, NHEAD), 128>>>(Wq);

    // Bias fold.
    c_kernel<<<1, B * NHEAD>>>(bq);

    // Main: (32 q-tiles of 64 rows, 16 batches), 256 threads, 68.1 KB smem.
    int smem = (NHEAD * EMB1 + HDIM + NHEAD) * (int)sizeof(float);
    static bool attr_set = false;
    if (!attr_set) {
        cudaFuncSetAttribute(main_kernel, cudaFuncAttributeMaxDynamicSharedMemorySize, smem);
        attr_set = true;
    }
    main_kernel<<<dim3(LQ / 64, B), 256, smem>>>(emb1, out);
}

// round 2
// speedup vs baseline: 1.2734x; 1.2734x over previous
#include <cuda_runtime.h>
#include <math.h>

#define B 16
#define LQ 2048
#define EMB1 1024
#define EMB2 768
#define HDIM 1024
#define NHEAD 16
#define DH 64

// Scratch (static device globals; no allocation in kernel_launch).
__device__ float g_K[B * HDIM];
__device__ float g_V[B * HDIM];
__device__ float g_Weff[B * NHEAD * EMB1];
__device__ float g_c[B * NHEAD];

// ---------------------------------------------------------------------------
// Kernel 1: K[b,j] = emb2[b]·Wk[j] + bk[j], V likewise. One warp per j,
// looping over batches so each Wk/Wv row is loaded once into registers.
// ---------------------------------------------------------------------------
__global__ void kv_kernel(const float* __restrict__ emb2,
                          const float* __restrict__ Wk, const float* __restrict__ bk,
                          const float* __restrict__ Wv, const float* __restrict__ bv) {
    int gwarp = (blockIdx.x * blockDim.x + threadIdx.x) >> 5;
    int lane = threadIdx.x & 31;
    if (gwarp >= HDIM) return;
    int j = gwarp;

    float wk[24], wv[24];
#pragma unroll
    for (int i = 0; i < 24; i++) {
        wk[i] = Wk[j * EMB2 + i * 32 + lane];
        wv[i] = Wv[j * EMB2 + i * 32 + lane];
    }
    float bkj = (lane == 0) ? bk[j] : 0.f;
    float bvj = (lane == 0) ? bv[j] : 0.f;

    for (int b = 0; b < B; b++) {
        float ak = 0.f, av = 0.f;
#pragma unroll
        for (int i = 0; i < 24; i++) {
            float e = emb2[b * EMB2 + i * 32 + lane];
            ak = fmaf(e, wk[i], ak);
            av = fmaf(e, wv[i], av);
        }
#pragma unroll
        for (int off = 16; off; off >>= 1) {
            ak += __shfl_xor_sync(0xffffffffu, ak, off);
            av += __shfl_xor_sync(0xffffffffu, av, off);
        }
        if (lane == 0) {
            g_K[b * HDIM + j] = ak + bkj;
            g_V[b * HDIM + j] = av + bvj;
        }
    }
}

// ---------------------------------------------------------------------------
// Kernel 2: Weff[b,h,e] = sum_d Wq[h*64+d, e] * K[b, h*64+d].
// Block = (e-chunk of 128, head h). Wq chunk staged in smem, reused for all b.
// ---------------------------------------------------------------------------
__global__ void weff_kernel(const float* __restrict__ Wq) {
    __shared__ float Wq_s[DH * 128];
    __shared__ float Ks[DH];
    int h = blockIdx.y;
    int e0 = blockIdx.x * 128;
    int tid = threadIdx.x;

#pragma unroll 8
    for (int d = 0; d < DH; d++)
        Wq_s[d * 128 + tid] = Wq[(h * DH + d) * EMB1 + e0 + tid];

    for (int b = 0; b < B; b++) {
        __syncthreads();
        if (tid < DH) Ks[tid] = g_K[b * HDIM + h * DH + tid];
        __syncthreads();
        float a = 0.f;
#pragma unroll 16
        for (int d = 0; d < DH; d++)
            a = fmaf(Wq_s[d * 128 + tid], Ks[d], a);
        g_Weff[(b * NHEAD + h) * EMB1 + e0 + tid] = a;
    }
}

// ---------------------------------------------------------------------------
// Kernel 3: c[b,h] = sum_d bq[h*64+d] * K[b, h*64+d]. One thread per (b,h).
// ---------------------------------------------------------------------------
__global__ void c_kernel(const float* __restrict__ bq) {
    int p = threadIdx.x;         // p = b*16 + h, 256 threads
    int b = p >> 4, h = p & 15;
    float a = 0.f;
#pragma unroll 16
    for (int d = 0; d < DH; d++)
        a = fmaf(bq[h * DH + d], g_K[b * HDIM + h * DH + d], a);
    g_c[p] = a;
}

// ---------------------------------------------------------------------------
// Kernel 4 (main): one warp per query row.
//   att[h] = emb1_row · Weff[b,h] + c[b,h]
//   out_row[h*64+d] = sigmoid(att[h]) * V[b, h*64+d]
// Weff[b] (64KB) + V[b] (4KB) + c[b] staged in dynamic smem per block.
//
// CRITICAL: __launch_bounds__(256, 3). With bare (256), ptxas targets 2048
// threads/SM and caps registers at 32 -> the 8x float4 row cache + 16
// accumulators spill to local memory (R1 evidence: regs=32, ~3GB DRAM
// traffic, issue 8.1%). (256,3) allows 85 regs, matching the smem-limited
// occupancy of 3 blocks/SM.
// ---------------------------------------------------------------------------
__global__ __launch_bounds__(256, 3) void main_kernel(const float* __restrict__ emb1,
                                                      float* __restrict__ out) {
    extern __shared__ float sm[];
    float* Weff_s = sm;                    // NHEAD*EMB1 = 16384 floats
    float* V_s = sm + NHEAD * EMB1;        // 1024 floats
    float* c_s = V_s + HDIM;               // 16 floats

    int b = blockIdx.y;
    int tid = threadIdx.x;

    // Cooperative staging
    {
        const float4* Wg = (const float4*)(g_Weff + (size_t)b * NHEAD * EMB1);
        float4* Ws4 = (float4*)Weff_s;
#pragma unroll
        for (int i = 0; i < NHEAD * EMB1 / 4 / 256; i++)
            Ws4[i * 256 + tid] = Wg[i * 256 + tid];
        const float4* Vg = (const float4*)(g_V + (size_t)b * HDIM);
        if (tid < HDIM / 4) ((float4*)V_s)[tid] = Vg[tid];
        if (tid < NHEAD) c_s[tid] = g_c[b * NHEAD + tid];
    }
    __syncthreads();

    int warp = tid >> 5, lane = tid & 31;
    const float4* Ws4 = (const float4*)Weff_s;
    const float4* Vs4 = (const float4*)V_s;
    int hi = (lane >> 4) & 1;

    for (int r = warp; r < 64; r += 8) {
        int q = blockIdx.x * 64 + r;
        const float4* xr = (const float4*)(emb1 + ((size_t)b * LQ + q) * EMB1);

        float4 x[8];
#pragma unroll
        for (int i = 0; i < 8; i++) x[i] = __ldg(&xr[i * 32 + lane]);

        float acc[NHEAD];
#pragma unroll
        for (int h = 0; h < NHEAD; h++) acc[h] = 0.f;

#pragma unroll
        for (int i = 0; i < 8; i++) {
#pragma unroll
            for (int h = 0; h < NHEAD; h++) {
                float4 w = Ws4[h * 256 + i * 32 + lane];
                acc[h] = fmaf(x[i].x, w.x, acc[h]);
                acc[h] = fmaf(x[i].y, w.y, acc[h]);
                acc[h] = fmaf(x[i].z, w.z, acc[h]);
                acc[h] = fmaf(x[i].w, w.w, acc[h]);
            }
        }

        // Butterfly reduce all 16 head accumulators across the warp.
#pragma unroll
        for (int off = 16; off; off >>= 1) {
#pragma unroll
            for (int h = 0; h < NHEAD; h++)
                acc[h] += __shfl_xor_sync(0xffffffffu, acc[h], off);
        }

        float sig[NHEAD];
#pragma unroll
        for (int h = 0; h < NHEAD; h++)
            sig[h] = __fdividef(1.f, 1.f + __expf(-(acc[h] + c_s[h])));

        float4* orow = (float4*)(out + ((size_t)b * LQ + q) * EMB1);
#pragma unroll
        for (int i = 0; i < 8; i++) {
            // float4 index i*32+lane covers hdim element 4*(i*32+lane);
            // head = (i*32+lane)>>4 = 2*i + (lane>=16)
            float s = sig[2 * i + hi];
            float4 v = Vs4[i * 32 + lane];
            float4 o;
            o.x = s * v.x; o.y = s * v.y; o.z = s * v.z; o.w = s * v.w;
            orow[i * 32 + lane] = o;
        }
    }
}

// ---------------------------------------------------------------------------
extern "C" void kernel_launch(void* const* d_in, const int* in_sizes, int n_in,
                              void* d_out, int out_size) {
    const float* emb1 = (const float*)d_in[0];
    const float* emb2 = (const float*)d_in[1];
    const float* Wq   = (const float*)d_in[2];
    const float* bq   = (const float*)d_in[3];
    const float* Wk   = (const float*)d_in[4];
    const float* bk   = (const float*)d_in[5];
    const float* Wv   = (const float*)d_in[6];
    const float* bv   = (const float*)d_in[7];
    float* out = (float*)d_out;

    // K/V projection: 1024 warps, 8 warps per block.
    kv_kernel<<<HDIM / 8, 256>>>(emb2, Wk, bk, Wv, bv);

    // Weff fold: (8 e-chunks, 16 heads), 128 threads.
    weff_kernel<<<dim3(EMB1 / 128, NHEAD), 128>>>(Wq);

    // Bias fold.
    c_kernel<<<1, B * NHEAD>>>(bq);

    // Main: (32 q-tiles of 64 rows, 16 batches), 256 threads, 68.1 KB smem.
    int smem = (NHEAD * EMB1 + HDIM + NHEAD) * (int)sizeof(float);
    static bool attr_set = false;
    if (!attr_set) {
        cudaFuncSetAttribute(main_kernel, cudaFuncAttributeMaxDynamicSharedMemorySize, smem);
        attr_set = true;
    }
    main_kernel<<<dim3(LQ / 64, B), 256, smem>>>(emb1, out);
}

// round 3
// speedup vs baseline: 7.9328x; 6.2297x over previous
#include <cuda_runtime.h>
#include <math.h>

#define B 16
#define LQ 2048
#define EMB1 1024
#define EMB2 768
#define HDIM 1024
#define NHEAD 16
#define DH 64
#define GRIDX 27   // 27*16 = 432 blocks <= 444 concurrent slots (148 SMs x 3 blocks)

// Scratch (static device globals; no allocation in kernel_launch).
__device__ float g_K[B * HDIM];
__device__ float g_V[B * HDIM];
__device__ float g_Weff[B * NHEAD * EMB1];
__device__ float g_c[B * NHEAD];

// ---------------------------------------------------------------------------
// Kernel 1: K[b,j] = emb2[b]·Wk[j] + bk[j], V likewise. One warp per j.
// ---------------------------------------------------------------------------
__global__ void kv_kernel(const float* __restrict__ emb2,
                          const float* __restrict__ Wk, const float* __restrict__ bk,
                          const float* __restrict__ Wv, const float* __restrict__ bv) {
    int gwarp = (blockIdx.x * blockDim.x + threadIdx.x) >> 5;
    int lane = threadIdx.x & 31;
    if (gwarp >= HDIM) return;
    int j = gwarp;

    float wk[24], wv[24];
#pragma unroll
    for (int i = 0; i < 24; i++) {
        wk[i] = Wk[j * EMB2 + i * 32 + lane];
        wv[i] = Wv[j * EMB2 + i * 32 + lane];
    }
    float bkj = (lane == 0) ? bk[j] : 0.f;
    float bvj = (lane == 0) ? bv[j] : 0.f;

    for (int b = 0; b < B; b++) {
        float ak = 0.f, av = 0.f;
#pragma unroll
        for (int i = 0; i < 24; i++) {
            float e = emb2[b * EMB2 + i * 32 + lane];
            ak = fmaf(e, wk[i], ak);
            av = fmaf(e, wv[i], av);
        }
#pragma unroll
        for (int off = 16; off; off >>= 1) {
            ak += __shfl_xor_sync(0xffffffffu, ak, off);
            av += __shfl_xor_sync(0xffffffffu, av, off);
        }
        if (lane == 0) {
            g_K[b * HDIM + j] = ak + bkj;
            g_V[b * HDIM + j] = av + bvj;
        }
    }
}

// ---------------------------------------------------------------------------
// Kernel 2: Weff[b,h,e] = sum_d Wq[h*64+d, e] * K[b, h*64+d].
// Also folds in c[b,h] = bq[h..]·K[b,h..] on the bx==0 blocks.
// ---------------------------------------------------------------------------
__global__ void weff_kernel(const float* __restrict__ Wq, const float* __restrict__ bq) {
    __shared__ float Wq_s[DH * 128];
    __shared__ float Ks[DH];
    int h = blockIdx.y;
    int e0 = blockIdx.x * 128;
    int tid = threadIdx.x;

    if (blockIdx.x == 0 && tid < B) {
        float a = 0.f;
#pragma unroll 16
        for (int d = 0; d < DH; d++)
            a = fmaf(bq[h * DH + d], g_K[tid * HDIM + h * DH + d], a);
        g_c[tid * NHEAD + h] = a;
    }

#pragma unroll 8
    for (int d = 0; d < DH; d++)
        Wq_s[d * 128 + tid] = Wq[(h * DH + d) * EMB1 + e0 + tid];

    for (int b = 0; b < B; b++) {
        __syncthreads();
        if (tid < DH) Ks[tid] = g_K[b * HDIM + h * DH + tid];
        __syncthreads();
        float a = 0.f;
#pragma unroll 16
        for (int d = 0; d < DH; d++)
            a = fmaf(Wq_s[d * 128 + tid], Ks[d], a);
        g_Weff[(b * NHEAD + h) * EMB1 + e0 + tid] = a;
    }
}

// ---------------------------------------------------------------------------
// Kernel 3 (main). Warp processes ROW PAIRS (w reused for 2 rows -> half the
// LDS traffic), with software-pipelined x loads. Folded butterfly reduction:
// after 5 steps lane l holds the full sum for head (l & 15); one sigmoid per
// row per lane; per-chunk head values distributed via shfl.idx.
// ---------------------------------------------------------------------------
__global__ __launch_bounds__(256, 3) void main_kernel(const float* __restrict__ emb1,
                                                      float* __restrict__ out) {
    extern __shared__ float sm[];
    float* Weff_s = sm;                    // 16384 floats
    float* V_s = sm + NHEAD * EMB1;        // 1024 floats
    float* c_s = V_s + HDIM;               // 16 floats

    int b = blockIdx.y;
    int tid = threadIdx.x;

    // Cooperative staging of Weff[b], V[b], c[b]
    {
        const float4* Wg = (const float4*)(g_Weff + (size_t)b * NHEAD * EMB1);
        float4* Ws4 = (float4*)Weff_s;
#pragma unroll
        for (int i = 0; i < NHEAD * EMB1 / 4 / 256; i++)
            Ws4[i * 256 + tid] = Wg[i * 256 + tid];
        const float4* Vg = (const float4*)(g_V + (size_t)b * HDIM);
        if (tid < HDIM / 4) ((float4*)V_s)[tid] = Vg[tid];
        if (tid < NHEAD) c_s[tid] = g_c[b * NHEAD + tid];
    }
    __syncthreads();

    int warp = tid >> 5, lane = tid & 31;
    const float4* Ws4 = (const float4*)Weff_s;
    const float4* Vs4 = (const float4*)V_s;
    int hi = lane >> 4;             // which head-parity this lane's float4s hit
    float c_l = c_s[lane & 15];     // head owned by this lane after the fold

    // Row pairs: 1024 per batch, strided over 27 blocks x 8 warps = 216 warps.
    for (int p = blockIdx.x * 8 + warp; p < LQ / 2; p += GRIDX * 8) {
        const float4* x0p = (const float4*)(emb1 + ((size_t)b * LQ + 2 * p) * EMB1);
        const float4* x1p = x0p + EMB1 / 4;

        float4 x0 = __ldg(x0p + lane);
        float4 x1 = __ldg(x1p + lane);

        float acc0[NHEAD], acc1[NHEAD];
#pragma unroll
        for (int h = 0; h < NHEAD; h++) { acc0[h] = 0.f; acc1[h] = 0.f; }

#pragma unroll
        for (int i = 0; i < 8; i++) {
            float4 x0n, x1n;
            if (i < 7) {                               // prefetch next chunk
                x0n = __ldg(x0p + (i + 1) * 32 + lane);
                x1n = __ldg(x1p + (i + 1) * 32 + lane);
            }
#pragma unroll
            for (int h = 0; h < NHEAD; h++) {
                float4 w = Ws4[h * 256 + i * 32 + lane];
                acc0[h] = fmaf(x0.x, w.x, acc0[h]);
                acc0[h] = fmaf(x0.y, w.y, acc0[h]);
                acc0[h] = fmaf(x0.z, w.z, acc0[h]);
                acc0[h] = fmaf(x0.w, w.w, acc0[h]);
                acc1[h] = fmaf(x1.x, w.x, acc1[h]);
                acc1[h] = fmaf(x1.y, w.y, acc1[h]);
                acc1[h] = fmaf(x1.z, w.z, acc1[h]);
                acc1[h] = fmaf(x1.w, w.w, acc1[h]);
            }
            if (i < 7) { x0 = x0n; x1 = x1n; }
        }

        // Folded reduction: 16 values x 32 lanes -> lane l holds head (l&15).
#pragma unroll
        for (int s = 0; s < 4; s++) {
            int o = 1 << s;
            int bit = (lane >> s) & 1;
#pragma unroll
            for (int j = 0; j < (8 >> s); j++) {
                float k0 = bit ? acc0[2 * j + 1] : acc0[2 * j];
                float s0 = bit ? acc0[2 * j] : acc0[2 * j + 1];
                acc0[j] = k0 + __shfl_xor_sync(0xffffffffu, s0, o);
                float k1 = bit ? acc1[2 * j + 1] : acc1[2 * j];
                float s1 = bit ? acc1[2 * j] : acc1[2 * j + 1];
                acc1[j] = k1 + __shfl_xor_sync(0xffffffffu, s1, o);
            }
        }
        acc0[0] += __shfl_xor_sync(0xffffffffu, acc0[0], 16);
        acc1[0] += __shfl_xor_sync(0xffffffffu, acc1[0], 16);

        float sig0 = __fdividef(1.f, 1.f + __expf(-(acc0[0] + c_l)));
        float sig1 = __fdividef(1.f, 1.f + __expf(-(acc1[0] + c_l)));

        float4* o0 = (float4*)(out + ((size_t)b * LQ + 2 * p) * EMB1);
        float4* o1 = o0 + EMB1 / 4;
#pragma unroll
        for (int i = 0; i < 8; i++) {
            // float4 (i*32+lane) belongs to head 2i + hi; lane (2i+hi) holds it.
            float s0 = __shfl_sync(0xffffffffu, sig0, 2 * i + hi);
            float s1 = __shfl_sync(0xffffffffu, sig1, 2 * i + hi);
            float4 v = Vs4[i * 32 + lane];
            float4 r0, r1;
            r0.x = s0 * v.x; r0.y = s0 * v.y; r0.z = s0 * v.z; r0.w = s0 * v.w;
            r1.x = s1 * v.x; r1.y = s1 * v.y; r1.z = s1 * v.z; r1.w = s1 * v.w;
            o0[i * 32 + lane] = r0;
            o1[i * 32 + lane] = r1;
        }
    }
}

// ---------------------------------------------------------------------------
extern "C" void kernel_launch(void* const* d_in, const int* in_sizes, int n_in,
                              void* d_out, int out_size) {
    const float* emb1 = (const float*)d_in[0];
    const float* emb2 = (const float*)d_in[1];
    const float* Wq   = (const float*)d_in[2];
    const float* bq   = (const float*)d_in[3];
    const float* Wk   = (const float*)d_in[4];
    const float* bk   = (const float*)d_in[5];
    const float* Wv   = (const float*)d_in[6];
    const float* bv   = (const float*)d_in[7];
    float* out = (float*)d_out;

    kv_kernel<<<HDIM / 8, 256>>>(emb2, Wk, bk, Wv, bv);
    weff_kernel<<<dim3(EMB1 / 128, NHEAD), 128>>>(Wq, bq);

    int smem = (NHEAD * EMB1 + HDIM + NHEAD) * (int)sizeof(float);
    static bool attr_set = false;
    if (!attr_set) {
        cudaFuncSetAttribute(main_kernel, cudaFuncAttributeMaxDynamicSharedMemorySize, smem);
        attr_set = true;
    }
    main_kernel<<<dim3(GRIDX, B), 256, smem>>>(emb1, out);
}